// round 1
// baseline (speedup 1.0000x reference)
#include <cuda_runtime.h>
#include <cstddef>
#include <cstdint>

#define E_BONDS   200000
#define NATOMS    100000
#define HID       128
#define MAX_NB    15
#define BFD       23      // ATOM_FDIM + BOND_FDIM
#define AFD       18      // ATOM_FDIM
#define AIN       146     // AFD + HID
#define NMOLS     2000
#define NPASS     5       // DEPTH - 1

// ---- scratch (device globals: alloc-free, graph-capturable) ----
__device__ float g_binput[(size_t)E_BONDS * HID];
__device__ float g_msgA  [(size_t)E_BONDS * HID];
__device__ float g_msgB  [(size_t)E_BONDS * HID];
__device__ float g_atomh [(size_t)NATOMS  * HID];

// ============================================================
// Kernel 1: binput = fbonds @ W_i ; msgA = relu(binput)
// 128 threads/block, thread = output column, grid-stride rows.
// ============================================================
__global__ void k_binput(const float* __restrict__ fbonds,
                         const float* __restrict__ W_i)
{
    __shared__ float Wsh[BFD][HID];
    int t = threadIdx.x; // 0..127
    for (int i = t; i < BFD * HID; i += 128) Wsh[i / HID][i % HID] = W_i[i];
    __syncthreads();

    for (int row = blockIdx.x; row < E_BONDS; row += gridDim.x) {
        const float* fr = fbonds + (size_t)row * BFD;
        float acc = 0.f;
        #pragma unroll
        for (int k = 0; k < BFD; k++) acc += __ldg(fr + k) * Wsh[k][t];
        size_t o = (size_t)row * HID + t;
        g_binput[o] = acc;
        g_msgA[o]   = fmaxf(acc, 0.f);
    }
}

// ============================================================
// Kernel 2: one message-passing step.
//   nei[e]    = sum_nb msg_in[bgraph[e][nb]]
//   msg_out[e]= relu(binput[e] + nei[e] @ W_h)
// 256 threads, TILE = 32 rows, persistent grid-stride over tiles.
// Dyn smem: Wsh[128][128] (64KB) + nei[128][36] k-major (18KB) + idx (2KB)
// GEMM: thread (cg = t&31, rg = t>>5) owns cols {4cg..4cg+3} x rows {4rg..4rg+3}
//   per k: 1 float4 LDS (W row) + 1 float4 broadcast LDS (nei) + 16 FMA.
// ============================================================
__global__ __launch_bounds__(256, 2)
void k_msgpass(const int* __restrict__ bgraph,
               const float* __restrict__ W_h,
               int flag)  // 0: A->B, 1: B->A
{
    extern __shared__ float smem[];
    float* Wsh = smem;                         // 128*128
    float* nei = smem + HID * HID;             // [k][r] 128*36 (pad 36 keeps f4 align)
    int*   idx = (int*)(nei + HID * 36);       // [32][16]

    const float* __restrict__ msg_in  = flag ? g_msgB : g_msgA;
    float*       __restrict__ msg_out = flag ? g_msgA : g_msgB;

    int t = threadIdx.x;

    // load W_h once per block (vectorized)
    for (int i = t; i < (HID * HID) / 4; i += 256)
        ((float4*)Wsh)[i] = ((const float4*)W_h)[i];
    __syncthreads();

    const int ntiles = (E_BONDS + 31) / 32;
    for (int tile = blockIdx.x; tile < ntiles; tile += gridDim.x) {
        const int base = tile * 32;

        // stage neighbor indices
        for (int i = t; i < 32 * MAX_NB; i += 256) {
            int r = i / MAX_NB, nb = i - r * MAX_NB;
            int e = base + r;
            idx[r * 16 + nb] = (e < E_BONDS)
                ? __ldg(bgraph + (size_t)e * MAX_NB + nb) : 0;
        }
        __syncthreads();

        // gather-sum: thread (c = t&127, half = t>>7) handles 16 rows
        {
            int c = t & 127, half = t >> 7;
            #pragma unroll 1
            for (int r = half * 16; r < half * 16 + 16; r++) {
                float s = 0.f;
                #pragma unroll
                for (int nb = 0; nb < MAX_NB; nb++) {
                    int e = idx[r * 16 + nb];
                    s += __ldg(msg_in + (size_t)e * HID + c);
                }
                nei[c * 36 + r] = s;
            }
        }
        __syncthreads();

        // GEMM + bias(binput) + relu
        {
            int cg = t & 31, rg = t >> 5;
            float acc[4][4];
            #pragma unroll
            for (int i = 0; i < 4; i++) {
                int row = base + rg * 4 + i;
                float4 b = (row < E_BONDS)
                    ? *(const float4*)&g_binput[(size_t)row * HID + cg * 4]
                    : make_float4(0.f, 0.f, 0.f, 0.f);
                acc[i][0] = b.x; acc[i][1] = b.y; acc[i][2] = b.z; acc[i][3] = b.w;
            }
            #pragma unroll 8
            for (int k = 0; k < HID; k++) {
                float4 w  = *(const float4*)&Wsh[k * HID + cg * 4];
                float4 nv = *(const float4*)&nei[k * 36 + rg * 4];
                acc[0][0] += nv.x * w.x; acc[0][1] += nv.x * w.y;
                acc[0][2] += nv.x * w.z; acc[0][3] += nv.x * w.w;
                acc[1][0] += nv.y * w.x; acc[1][1] += nv.y * w.y;
                acc[1][2] += nv.y * w.z; acc[1][3] += nv.y * w.w;
                acc[2][0] += nv.z * w.x; acc[2][1] += nv.z * w.y;
                acc[2][2] += nv.z * w.z; acc[2][3] += nv.z * w.w;
                acc[3][0] += nv.w * w.x; acc[3][1] += nv.w * w.y;
                acc[3][2] += nv.w * w.z; acc[3][3] += nv.w * w.w;
            }
            #pragma unroll
            for (int i = 0; i < 4; i++) {
                int row = base + rg * 4 + i;
                if (row < E_BONDS) {
                    float4 o;
                    o.x = fmaxf(acc[i][0], 0.f); o.y = fmaxf(acc[i][1], 0.f);
                    o.z = fmaxf(acc[i][2], 0.f); o.w = fmaxf(acc[i][3], 0.f);
                    *(float4*)&msg_out[(size_t)row * HID + cg * 4] = o;
                }
            }
        }
        __syncthreads();
    }
}

// ============================================================
// Kernel 3: atom readout.
//   nei_a[a] = sum_nb msgB[agraph[a][nb]]
//   atomh[a] = relu([fatoms[a] | nei_a[a]] @ W_o + b_o)
// Same tiling, K = 146.
// ============================================================
__global__ __launch_bounds__(256, 2)
void k_atomh(const float* __restrict__ fatoms,
             const int*   __restrict__ agraph,
             const float* __restrict__ W_o,
             const float* __restrict__ b_o)
{
    extern __shared__ float smem[];
    float* Wsh = smem;                          // [146][128]
    float* ain = smem + AIN * HID;              // [146][36]
    int*   idx = (int*)(ain + AIN * 36);        // [32][16]
    __shared__ float bsh[HID];

    int t = threadIdx.x;
    for (int i = t; i < (AIN * HID) / 4; i += 256)
        ((float4*)Wsh)[i] = ((const float4*)W_o)[i];
    if (t < HID) bsh[t] = b_o[t];
    __syncthreads();

    const int ntiles = (NATOMS + 31) / 32;
    for (int tile = blockIdx.x; tile < ntiles; tile += gridDim.x) {
        const int base = tile * 32;

        for (int i = t; i < 32 * MAX_NB; i += 256) {
            int r = i / MAX_NB, nb = i - r * MAX_NB;
            int a = base + r;
            idx[r * 16 + nb] = (a < NATOMS)
                ? __ldg(agraph + (size_t)a * MAX_NB + nb) : 0;
        }
        // fatoms rows (k < 18) of ain
        for (int i = t; i < AFD * 32; i += 256) {
            int k = i >> 5, r = i & 31;
            int a = base + r;
            ain[k * 36 + r] = (a < NATOMS)
                ? __ldg(fatoms + (size_t)a * AFD + k) : 0.f;
        }
        __syncthreads();

        // gather rows 18..145
        {
            int c = t & 127, half = t >> 7;
            #pragma unroll 1
            for (int r = half * 16; r < half * 16 + 16; r++) {
                float s = 0.f;
                #pragma unroll
                for (int nb = 0; nb < MAX_NB; nb++) {
                    int e = idx[r * 16 + nb];
                    s += __ldg(g_msgB + (size_t)e * HID + c);
                }
                ain[(AFD + c) * 36 + r] = s;
            }
        }
        __syncthreads();

        {
            int cg = t & 31, rg = t >> 5;
            float acc[4][4];
            #pragma unroll
            for (int i = 0; i < 4; i++) {
                acc[i][0] = bsh[cg * 4 + 0]; acc[i][1] = bsh[cg * 4 + 1];
                acc[i][2] = bsh[cg * 4 + 2]; acc[i][3] = bsh[cg * 4 + 3];
            }
            #pragma unroll 2
            for (int k = 0; k < AIN; k++) {
                float4 w  = *(const float4*)&Wsh[k * HID + cg * 4];
                float4 nv = *(const float4*)&ain[k * 36 + rg * 4];
                acc[0][0] += nv.x * w.x; acc[0][1] += nv.x * w.y;
                acc[0][2] += nv.x * w.z; acc[0][3] += nv.x * w.w;
                acc[1][0] += nv.y * w.x; acc[1][1] += nv.y * w.y;
                acc[1][2] += nv.y * w.z; acc[1][3] += nv.y * w.w;
                acc[2][0] += nv.z * w.x; acc[2][1] += nv.z * w.y;
                acc[2][2] += nv.z * w.z; acc[2][3] += nv.z * w.w;
                acc[3][0] += nv.w * w.x; acc[3][1] += nv.w * w.y;
                acc[3][2] += nv.w * w.z; acc[3][3] += nv.w * w.w;
            }
            #pragma unroll
            for (int i = 0; i < 4; i++) {
                int a = base + rg * 4 + i;
                if (a < NATOMS) {
                    float4 o;
                    o.x = fmaxf(acc[i][0], 0.f); o.y = fmaxf(acc[i][1], 0.f);
                    o.z = fmaxf(acc[i][2], 0.f); o.w = fmaxf(acc[i][3], 0.f);
                    *(float4*)&g_atomh[(size_t)a * HID + cg * 4] = o;
                }
            }
        }
        __syncthreads();
    }
}

// ============================================================
// Kernel 4: segment mean pooling. block = one molecule.
// ============================================================
__global__ void k_pool(const int* __restrict__ scope_start,
                       const int* __restrict__ scope_len,
                       float* __restrict__ out)
{
    int m = blockIdx.x, t = threadIdx.x; // 128 threads
    int s = scope_start[m], L = scope_len[m];
    float acc = 0.f;
    for (int i = 0; i < L; i++)
        acc += g_atomh[(size_t)(s + i) * HID + t];
    out[(size_t)m * HID + t] = acc / (float)L;
}

// ============================================================
extern "C" void kernel_launch(void* const* d_in, const int* in_sizes, int n_in,
                              void* d_out, int out_size)
{
    const float* fatoms      = (const float*)d_in[0];
    const float* fbonds      = (const float*)d_in[1];
    const int*   agraph      = (const int*)  d_in[2];
    const int*   bgraph      = (const int*)  d_in[3];
    const int*   scope_start = (const int*)  d_in[4];
    const int*   scope_len   = (const int*)  d_in[5];
    const float* W_i         = (const float*)d_in[6];
    const float* W_h         = (const float*)d_in[7];
    const float* W_o         = (const float*)d_in[8];
    const float* b_o         = (const float*)d_in[9];
    float* out = (float*)d_out;

    const int SMEM2 = (HID * HID + HID * 36) * 4 + 32 * 16 * 4;   // 86016
    const int SMEM3 = (AIN * HID + AIN * 36) * 4 + 32 * 16 * 4;   // 97824

    cudaFuncSetAttribute(k_msgpass, cudaFuncAttributeMaxDynamicSharedMemorySize, SMEM2);
    cudaFuncSetAttribute(k_atomh,   cudaFuncAttributeMaxDynamicSharedMemorySize, SMEM3);

    k_binput<<<2048, 128>>>(fbonds, W_i);

    for (int d = 0; d < NPASS; d++)
        k_msgpass<<<304, 256, SMEM2>>>(bgraph, W_h, d & 1);

    k_atomh<<<304, 256, SMEM3>>>(fatoms, agraph, W_o, b_o);

    k_pool<<<NMOLS, 128>>>(scope_start, scope_len, out);
}

// round 2
// speedup vs baseline: 1.4557x; 1.4557x over previous
#include <cuda_runtime.h>
#include <cstddef>
#include <cstdint>

#define E_BONDS   200000
#define NATOMS    100000
#define HID       128
#define MAX_NB    15
#define BFD       23      // ATOM_FDIM + BOND_FDIM
#define AFD       18      // ATOM_FDIM
#define AIN       146     // AFD + HID
#define NMOLS     2000
#define NPASS     5       // DEPTH - 1

// ---- scratch (device globals: alloc-free, graph-capturable) ----
__device__ float g_binput[(size_t)E_BONDS * HID];
__device__ float g_msgA  [(size_t)E_BONDS * HID];
__device__ float g_msgB  [(size_t)E_BONDS * HID];
__device__ float g_atomh [(size_t)NATOMS  * HID];

// ---- packed f32x2 helpers (sm_103a) ----
__device__ __forceinline__ unsigned long long pack2(float lo, float hi) {
    unsigned long long r;
    asm("mov.b64 %0, {%1, %2};" : "=l"(r) : "f"(lo), "f"(hi));
    return r;
}
__device__ __forceinline__ void unpack2(unsigned long long v, float& lo, float& hi) {
    asm("mov.b64 {%0, %1}, %2;" : "=f"(lo), "=f"(hi) : "l"(v));
}
__device__ __forceinline__ void ffma2(unsigned long long& d,
                                      unsigned long long a, unsigned long long b) {
    asm("fma.rn.f32x2 %0, %1, %2, %0;" : "+l"(d) : "l"(a), "l"(b));
}

// ============================================================
// Kernel 1: binput = fbonds @ W_i ; msgA = relu(binput)
// One warp per row; lane owns 4 output cols (float4 stores).
// ============================================================
__global__ __launch_bounds__(256)
void k_binput(const float* __restrict__ fbonds,
              const float* __restrict__ W_i)
{
    __shared__ float Wsh[BFD * HID];
    int t = threadIdx.x;
    for (int i = t; i < BFD * HID; i += 256) Wsh[i] = W_i[i];
    __syncthreads();

    int c4 = t & 31, w = t >> 5;
    int gw = blockIdx.x * 8 + w;
    const int nwarps = gridDim.x * 8;

    for (int row = gw; row < E_BONDS; row += nwarps) {
        const float* fr = fbonds + (size_t)row * BFD;
        float4 acc = make_float4(0.f, 0.f, 0.f, 0.f);
        #pragma unroll
        for (int k = 0; k < BFD; k++) {
            float f = __ldg(fr + k);
            float4 wv = *(const float4*)&Wsh[k * HID + c4 * 4];
            acc.x += f * wv.x; acc.y += f * wv.y;
            acc.z += f * wv.z; acc.w += f * wv.w;
        }
        size_t o = (size_t)row * HID + c4 * 4;
        *(float4*)&g_binput[o] = acc;
        float4 rr;
        rr.x = fmaxf(acc.x, 0.f); rr.y = fmaxf(acc.y, 0.f);
        rr.z = fmaxf(acc.z, 0.f); rr.w = fmaxf(acc.w, 0.f);
        *(float4*)&g_msgA[o] = rr;
    }
}

// ============================================================
// Kernel 2: one message-passing step.
//   nei[e]    = sum_nb msg_in[bgraph[e][nb]]
//   msg_out[e]= relu(binput[e] + nei[e] @ W_h)
// 256 thr, TILE=32 rows. Gather: warp w loads full 512B rows
// (float4/lane) for rows 4w..4w+3. Transposed store into smem
// with rotation swizzle (conflict-free). GEMM: 4x4 reg tile per
// thread using packed fma.rn.f32x2.
// smem: Wsh 64KB + nei[128][32] 16KB + idx 2KB = 84KB -> 2 blk/SM
// ============================================================
__global__ __launch_bounds__(256, 2)
void k_msgpass(const int* __restrict__ bgraph,
               const float* __restrict__ W_h,
               int flag)  // 0: A->B, 1: B->A
{
    extern __shared__ float smem[];
    float* Wsh = smem;                       // [128][128]
    float* nei = smem + HID * HID;           // [128][32] swizzled
    int*   idx = (int*)(nei + HID * 32);     // [32][16]

    const float* __restrict__ msg_in  = flag ? g_msgB : g_msgA;
    float*       __restrict__ msg_out = flag ? g_msgA : g_msgB;

    const int t = threadIdx.x;
    const int c4 = t & 31;      // lane
    const int wg = t >> 5;      // warp / row-group

    for (int i = t; i < (HID * HID) / 4; i += 256)
        ((float4*)Wsh)[i] = ((const float4*)W_h)[i];
    __syncthreads();

    const int ntiles = E_BONDS / 32;
    for (int tile = blockIdx.x; tile < ntiles; tile += gridDim.x) {
        const int base = tile * 32;

        // stage neighbor indices
        for (int i = t; i < 32 * MAX_NB; i += 256) {
            int r = i / MAX_NB, nb = i - r * MAX_NB;
            idx[r * 16 + nb] = __ldg(bgraph + (size_t)(base + r) * MAX_NB + nb);
        }
        __syncthreads();

        // gather-sum: warp wg handles rows 4wg..4wg+3, lane c4 owns 16B slice
        #pragma unroll
        for (int i = 0; i < 4; i++) {
            int r = wg * 4 + i;
            float sx = 0.f, sy = 0.f, sz = 0.f, sw = 0.f;
            #pragma unroll
            for (int nb = 0; nb < MAX_NB; nb++) {
                int e = idx[r * 16 + nb];
                float4 v = *(const float4*)(msg_in + (size_t)e * HID + c4 * 4);
                sx += v.x; sy += v.y; sz += v.z; sw += v.w;
            }
            int rot = (r + c4) & 31;    // rotation swizzle: bank = (r+c4)&31
            nei[(4 * c4 + 0) * 32 + rot] = sx;
            nei[(4 * c4 + 1) * 32 + rot] = sy;
            nei[(4 * c4 + 2) * 32 + rot] = sz;
            nei[(4 * c4 + 3) * 32 + rot] = sw;
        }
        __syncthreads();

        // GEMM + bias(binput) + relu — packed f32x2
        {
            const int r0 = wg * 4;
            unsigned long long acc[4][2];
            #pragma unroll
            for (int i = 0; i < 4; i++) {
                float4 b = *(const float4*)&g_binput[(size_t)(base + r0 + i) * HID + c4 * 4];
                acc[i][0] = pack2(b.x, b.y);
                acc[i][1] = pack2(b.z, b.w);
            }
            #pragma unroll 4
            for (int k = 0; k < HID; k++) {
                const int rot = k >> 2;
                const float* nb = &nei[k * 32];
                float n0 = nb[(r0 + 0 + rot) & 31];
                float n1 = nb[(r0 + 1 + rot) & 31];
                float n2 = nb[(r0 + 2 + rot) & 31];
                float n3 = nb[(r0 + 3 + rot) & 31];
                ulonglong2 wv = *(const ulonglong2*)&Wsh[k * HID + c4 * 4];
                unsigned long long p0 = pack2(n0, n0);
                unsigned long long p1 = pack2(n1, n1);
                unsigned long long p2 = pack2(n2, n2);
                unsigned long long p3 = pack2(n3, n3);
                ffma2(acc[0][0], p0, wv.x); ffma2(acc[0][1], p0, wv.y);
                ffma2(acc[1][0], p1, wv.x); ffma2(acc[1][1], p1, wv.y);
                ffma2(acc[2][0], p2, wv.x); ffma2(acc[2][1], p2, wv.y);
                ffma2(acc[3][0], p3, wv.x); ffma2(acc[3][1], p3, wv.y);
            }
            #pragma unroll
            for (int i = 0; i < 4; i++) {
                float4 o;
                unpack2(acc[i][0], o.x, o.y);
                unpack2(acc[i][1], o.z, o.w);
                o.x = fmaxf(o.x, 0.f); o.y = fmaxf(o.y, 0.f);
                o.z = fmaxf(o.z, 0.f); o.w = fmaxf(o.w, 0.f);
                *(float4*)&msg_out[(size_t)(base + r0 + i) * HID + c4 * 4] = o;
            }
        }
        __syncthreads();
    }
}

// ============================================================
// Kernel 3: atom readout (same scheme, K = 146).
// ============================================================
__global__ __launch_bounds__(256, 2)
void k_atomh(const float* __restrict__ fatoms,
             const int*   __restrict__ agraph,
             const float* __restrict__ W_o,
             const float* __restrict__ b_o)
{
    extern __shared__ float smem[];
    float* Wsh = smem;                       // [146][128]
    float* ain = smem + AIN * HID;           // [146][32] swizzled
    int*   idx = (int*)(ain + AIN * 32);     // [32][16]
    __shared__ float bsh[HID];

    const int t = threadIdx.x;
    const int c4 = t & 31;
    const int wg = t >> 5;

    for (int i = t; i < (AIN * HID) / 4; i += 256)
        ((float4*)Wsh)[i] = ((const float4*)W_o)[i];
    if (t < HID) bsh[t] = b_o[t];
    __syncthreads();

    const int ntiles = NATOMS / 32;
    for (int tile = blockIdx.x; tile < ntiles; tile += gridDim.x) {
        const int base = tile * 32;

        for (int i = t; i < 32 * MAX_NB; i += 256) {
            int r = i / MAX_NB, nb = i - r * MAX_NB;
            idx[r * 16 + nb] = __ldg(agraph + (size_t)(base + r) * MAX_NB + nb);
        }
        // fatoms rows (k = 0..17), swizzled
        for (int i = t; i < AFD * 32; i += 256) {
            int k = i >> 5, r = i & 31;
            ain[k * 32 + ((r + (k >> 2)) & 31)] =
                __ldg(fatoms + (size_t)(base + r) * AFD + k);
        }
        __syncthreads();

        // gather rows k = 18..145
        #pragma unroll
        for (int i = 0; i < 4; i++) {
            int r = wg * 4 + i;
            float sx = 0.f, sy = 0.f, sz = 0.f, sw = 0.f;
            #pragma unroll
            for (int nb = 0; nb < MAX_NB; nb++) {
                int e = idx[r * 16 + nb];
                float4 v = *(const float4*)(g_msgB + (size_t)e * HID + c4 * 4);
                sx += v.x; sy += v.y; sz += v.z; sw += v.w;
            }
            int k0 = AFD + 4 * c4;
            ain[(k0 + 0) * 32 + ((r + ((k0 + 0) >> 2)) & 31)] = sx;
            ain[(k0 + 1) * 32 + ((r + ((k0 + 1) >> 2)) & 31)] = sy;
            ain[(k0 + 2) * 32 + ((r + ((k0 + 2) >> 2)) & 31)] = sz;
            ain[(k0 + 3) * 32 + ((r + ((k0 + 3) >> 2)) & 31)] = sw;
        }
        __syncthreads();

        {
            const int r0 = wg * 4;
            unsigned long long acc[4][2];
            unsigned long long b01 = pack2(bsh[c4 * 4 + 0], bsh[c4 * 4 + 1]);
            unsigned long long b23 = pack2(bsh[c4 * 4 + 2], bsh[c4 * 4 + 3]);
            #pragma unroll
            for (int i = 0; i < 4; i++) { acc[i][0] = b01; acc[i][1] = b23; }
            #pragma unroll 2
            for (int k = 0; k < AIN; k++) {
                const int rot = k >> 2;
                const float* nb = &ain[k * 32];
                float n0 = nb[(r0 + 0 + rot) & 31];
                float n1 = nb[(r0 + 1 + rot) & 31];
                float n2 = nb[(r0 + 2 + rot) & 31];
                float n3 = nb[(r0 + 3 + rot) & 31];
                ulonglong2 wv = *(const ulonglong2*)&Wsh[k * HID + c4 * 4];
                unsigned long long p0 = pack2(n0, n0);
                unsigned long long p1 = pack2(n1, n1);
                unsigned long long p2 = pack2(n2, n2);
                unsigned long long p3 = pack2(n3, n3);
                ffma2(acc[0][0], p0, wv.x); ffma2(acc[0][1], p0, wv.y);
                ffma2(acc[1][0], p1, wv.x); ffma2(acc[1][1], p1, wv.y);
                ffma2(acc[2][0], p2, wv.x); ffma2(acc[2][1], p2, wv.y);
                ffma2(acc[3][0], p3, wv.x); ffma2(acc[3][1], p3, wv.y);
            }
            #pragma unroll
            for (int i = 0; i < 4; i++) {
                float4 o;
                unpack2(acc[i][0], o.x, o.y);
                unpack2(acc[i][1], o.z, o.w);
                o.x = fmaxf(o.x, 0.f); o.y = fmaxf(o.y, 0.f);
                o.z = fmaxf(o.z, 0.f); o.w = fmaxf(o.w, 0.f);
                *(float4*)&g_atomh[(size_t)(base + r0 + i) * HID + c4 * 4] = o;
            }
        }
        __syncthreads();
    }
}

// ============================================================
// Kernel 4: segment mean pooling. block = one molecule.
// ============================================================
__global__ void k_pool(const int* __restrict__ scope_start,
                       const int* __restrict__ scope_len,
                       float* __restrict__ out)
{
    int m = blockIdx.x, t = threadIdx.x; // 128 threads
    int s = scope_start[m], L = scope_len[m];
    float acc = 0.f;
    for (int i = 0; i < L; i++)
        acc += g_atomh[(size_t)(s + i) * HID + t];
    out[(size_t)m * HID + t] = acc / (float)L;
}

// ============================================================
extern "C" void kernel_launch(void* const* d_in, const int* in_sizes, int n_in,
                              void* d_out, int out_size)
{
    const float* fatoms      = (const float*)d_in[0];
    const float* fbonds      = (const float*)d_in[1];
    const int*   agraph      = (const int*)  d_in[2];
    const int*   bgraph      = (const int*)  d_in[3];
    const int*   scope_start = (const int*)  d_in[4];
    const int*   scope_len   = (const int*)  d_in[5];
    const float* W_i         = (const float*)d_in[6];
    const float* W_h         = (const float*)d_in[7];
    const float* W_o         = (const float*)d_in[8];
    const float* b_o         = (const float*)d_in[9];
    float* out = (float*)d_out;

    const int SMEM2 = (HID * HID + HID * 32) * 4 + 32 * 16 * 4;   // 83968
    const int SMEM3 = (AIN * HID + AIN * 32) * 4 + 32 * 16 * 4;   // 95488

    cudaFuncSetAttribute(k_msgpass, cudaFuncAttributeMaxDynamicSharedMemorySize, SMEM2);
    cudaFuncSetAttribute(k_atomh,   cudaFuncAttributeMaxDynamicSharedMemorySize, SMEM3);

    k_binput<<<1024, 256>>>(fbonds, W_i);

    for (int d = 0; d < NPASS; d++)
        k_msgpass<<<304, 256, SMEM2>>>(bgraph, W_h, d & 1);

    k_atomh<<<304, 256, SMEM3>>>(fatoms, agraph, W_o, b_o);

    k_pool<<<NMOLS, 128>>>(scope_start, scope_len, out);
}